// round 3
// baseline (speedup 1.0000x reference)
#include <cuda_runtime.h>
#include <cstdint>

#define N_NODES 200000
#define N_EDGES 3200000
#define N_GRAPHS 4096
#define IN_CH 78
#define H1 64
#define H2 128
#define OUT_DIM 128

#define SCAN_B 512
#define SCAN_NBLK ((N_NODES + SCAN_B - 1) / SCAN_B)   // 391

// ---------------- device scratch (static globals; no allocation) ----------------
__device__ int    g_deg[N_NODES];          // in-degree incl self loop
__device__ float  g_dinv[N_NODES];
__device__ int    g_ptr[N_NODES];          // CSR offsets (exclusive scan of deg-1)
__device__ int    g_cursor[N_NODES];
__device__ int    g_bsum[SCAN_B];          // block sums for scan (SCAN_NBLK <= 512)
__device__ int2   g_csr[N_EDGES];          // {src, float_bits(norm)} sorted by dst
__device__ float  g_bufA[N_NODES * H1];    // hw1 = x@W1 ; later reused for agg2
__device__ float  g_h1[N_NODES * H1];      // relu(agg1 + b1)
__device__ float  g_h2[N_NODES * H2];      // relu(agg2@W2 + b2)
__device__ int    g_starts[N_GRAPHS + 1];

// ---------------- degree / dinv ----------------
__global__ void k_init_deg() {
    int i = blockIdx.x * blockDim.x + threadIdx.x;
    if (i < N_NODES) g_deg[i] = 1;   // self loop
}

__global__ void k_count(const int* __restrict__ ei) {
    int e = blockIdx.x * blockDim.x + threadIdx.x;
    if (e < N_EDGES) {
        int d = ei[N_EDGES + e];   // dst row
        atomicAdd(&g_deg[d], 1);
    }
}

__global__ void k_dinv() {
    int i = blockIdx.x * blockDim.x + threadIdx.x;
    if (i < N_NODES) g_dinv[i] = rsqrtf((float)g_deg[i]);
}

// ---------------- 3-pass exclusive scan of (deg-1) ----------------
__global__ void k_scan1() {
    __shared__ int s[SCAN_B];
    int i = blockIdx.x * SCAN_B + threadIdx.x;
    int v = (i < N_NODES) ? (g_deg[i] - 1) : 0;
    s[threadIdx.x] = v;
    __syncthreads();
    #pragma unroll
    for (int d = 1; d < SCAN_B; d <<= 1) {
        int t = (threadIdx.x >= d) ? s[threadIdx.x - d] : 0;
        __syncthreads();
        s[threadIdx.x] += t;
        __syncthreads();
    }
    if (i < N_NODES) g_ptr[i] = s[threadIdx.x] - v;   // exclusive within block
    if (threadIdx.x == SCAN_B - 1) g_bsum[blockIdx.x] = s[SCAN_B - 1];
}

__global__ void k_scan2() {
    __shared__ int s[SCAN_B];
    int v = (threadIdx.x < SCAN_NBLK) ? g_bsum[threadIdx.x] : 0;
    s[threadIdx.x] = v;
    __syncthreads();
    #pragma unroll
    for (int d = 1; d < SCAN_B; d <<= 1) {
        int t = (threadIdx.x >= d) ? s[threadIdx.x - d] : 0;
        __syncthreads();
        s[threadIdx.x] += t;
        __syncthreads();
    }
    if (threadIdx.x < SCAN_NBLK) g_bsum[threadIdx.x] = s[threadIdx.x] - v; // exclusive
}

__global__ void k_scan3() {
    int i = blockIdx.x * SCAN_B + threadIdx.x;
    if (i < N_NODES) {
        int p = g_ptr[i] + g_bsum[blockIdx.x];
        g_ptr[i] = p;
        g_cursor[i] = p;
    }
}

// ---------------- CSR scatter ----------------
__global__ void k_scatter(const int* __restrict__ ei) {
    int e = blockIdx.x * blockDim.x + threadIdx.x;
    if (e < N_EDGES) {
        int s = ei[e];
        int d = ei[N_EDGES + e];
        int pos = atomicAdd(&g_cursor[d], 1);
        float w = g_dinv[s] * g_dinv[d];
        g_csr[pos] = make_int2(s, __float_as_int(w));
    }
}

// ---------------- GEMM1: bufA[N,64] = x[N,78] @ W1[78,64] ----------------
__global__ void __launch_bounds__(256) k_gemm1(const float* __restrict__ X,
                                               const float* __restrict__ W) {
    __shared__ __align__(16) float xs[64 * 79];
    __shared__ __align__(16) float ws[IN_CH * H1];
    int n0 = blockIdx.x * 64;
    const float* xg = X + (size_t)n0 * IN_CH;
    for (int idx = threadIdx.x; idx < 64 * IN_CH; idx += 256) {
        int r = idx / IN_CH, c = idx - r * IN_CH;
        xs[r * 79 + c] = xg[idx];
    }
    for (int idx = threadIdx.x; idx < IN_CH * H1; idx += 256) ws[idx] = W[idx];
    __syncthreads();

    int tn = threadIdx.x >> 4;   // 0..15 -> 4 nodes each
    int tc = threadIdx.x & 15;   // 0..15 -> 4 cols each
    float acc[4][4] = {};
    #pragma unroll 2
    for (int k = 0; k < IN_CH; k++) {
        float4 wq = *(const float4*)&ws[k * H1 + tc * 4];
        #pragma unroll
        for (int i = 0; i < 4; i++) {
            float xv = xs[(tn * 4 + i) * 79 + k];
            acc[i][0] += xv * wq.x;
            acc[i][1] += xv * wq.y;
            acc[i][2] += xv * wq.z;
            acc[i][3] += xv * wq.w;
        }
    }
    #pragma unroll
    for (int i = 0; i < 4; i++) {
        float4 o = make_float4(acc[i][0], acc[i][1], acc[i][2], acc[i][3]);
        *(float4*)&g_bufA[(size_t)(n0 + tn * 4 + i) * H1 + tc * 4] = o;
    }
}

// ---------------- aggregation: one warp per node, 64-dim features ----------------
// hout[n] = sum_{e in CSR(n)} w_e * hin[src_e] + dinv[n]^2 * hin[n]  (+bias, relu)
// Buffer selection is compile-time (DIR): 0 = bufA -> h1 (bias+relu), 1 = h1 -> bufA.
template <int DIR>
__global__ void __launch_bounds__(256) k_agg(const float* __restrict__ bias) {
    const float* hin  = (DIR == 0) ? g_bufA : g_h1;
    float*       hout = (DIR == 0) ? g_h1   : g_bufA;

    int w = (blockIdx.x * blockDim.x + threadIdx.x) >> 5;
    if (w >= N_NODES) return;
    int lane = threadIdx.x & 31;
    int start = g_ptr[w];
    int cnt = g_deg[w] - 1;
    float di = g_dinv[w];
    const float2* hp = (const float2*)hin;

    float2 sv = hp[(size_t)w * 32 + lane];
    float w0 = di * di;
    float ax = sv.x * w0, ay = sv.y * w0;

    int e = 0;
    for (; e + 4 <= cnt; e += 4) {
        int2 m0 = g_csr[start + e + 0];
        int2 m1 = g_csr[start + e + 1];
        int2 m2 = g_csr[start + e + 2];
        int2 m3 = g_csr[start + e + 3];
        float2 v0 = hp[(size_t)m0.x * 32 + lane];
        float2 v1 = hp[(size_t)m1.x * 32 + lane];
        float2 v2 = hp[(size_t)m2.x * 32 + lane];
        float2 v3 = hp[(size_t)m3.x * 32 + lane];
        float w0f = __int_as_float(m0.y), w1f = __int_as_float(m1.y);
        float w2f = __int_as_float(m2.y), w3f = __int_as_float(m3.y);
        ax += w0f * v0.x; ay += w0f * v0.y;
        ax += w1f * v1.x; ay += w1f * v1.y;
        ax += w2f * v2.x; ay += w2f * v2.y;
        ax += w3f * v3.x; ay += w3f * v3.y;
    }
    for (; e < cnt; e++) {
        int2 m = g_csr[start + e];
        float2 v = hp[(size_t)m.x * 32 + lane];
        float wf = __int_as_float(m.y);
        ax += wf * v.x; ay += wf * v.y;
    }
    if (DIR == 0) {
        ax = fmaxf(ax + bias[2 * lane], 0.0f);
        ay = fmaxf(ay + bias[2 * lane + 1], 0.0f);
    }
    ((float2*)hout)[(size_t)w * 32 + lane] = make_float2(ax, ay);
}

// ---------------- GEMM2: h2[N,128] = relu(agg2[N,64] @ W2[64,128] + b2) ----------------
__global__ void __launch_bounds__(128) k_gemm2(const float* __restrict__ W2,
                                               const float* __restrict__ b2) {
    __shared__ __align__(16) float as[32 * 65];
    __shared__ __align__(16) float ws[H1 * H2];
    int n0 = blockIdx.x * 32;
    const float* ag = g_bufA + (size_t)n0 * H1;
    for (int idx = threadIdx.x; idx < 32 * H1; idx += 128) {
        int r = idx >> 6, c = idx & 63;
        as[r * 65 + c] = ag[idx];
    }
    for (int idx = threadIdx.x; idx < H1 * H2; idx += 128) ws[idx] = W2[idx];
    __syncthreads();

    int tn = threadIdx.x >> 4;   // 0..7 -> 4 nodes each
    int tc = threadIdx.x & 15;   // 0..15 -> 8 cols each
    float acc[4][8] = {};
    #pragma unroll 2
    for (int k = 0; k < H1; k++) {
        float4 w0 = *(const float4*)&ws[k * H2 + tc * 8];
        float4 w1 = *(const float4*)&ws[k * H2 + tc * 8 + 4];
        #pragma unroll
        for (int i = 0; i < 4; i++) {
            float av = as[(tn * 4 + i) * 65 + k];
            acc[i][0] += av * w0.x; acc[i][1] += av * w0.y;
            acc[i][2] += av * w0.z; acc[i][3] += av * w0.w;
            acc[i][4] += av * w1.x; acc[i][5] += av * w1.y;
            acc[i][6] += av * w1.z; acc[i][7] += av * w1.w;
        }
    }
    float4 bq0 = *(const float4*)&b2[tc * 8];
    float4 bq1 = *(const float4*)&b2[tc * 8 + 4];
    #pragma unroll
    for (int i = 0; i < 4; i++) {
        float4 o0 = make_float4(fmaxf(acc[i][0] + bq0.x, 0.f), fmaxf(acc[i][1] + bq0.y, 0.f),
                                fmaxf(acc[i][2] + bq0.z, 0.f), fmaxf(acc[i][3] + bq0.w, 0.f));
        float4 o1 = make_float4(fmaxf(acc[i][4] + bq1.x, 0.f), fmaxf(acc[i][5] + bq1.y, 0.f),
                                fmaxf(acc[i][6] + bq1.z, 0.f), fmaxf(acc[i][7] + bq1.w, 0.f));
        size_t row = (size_t)(n0 + tn * 4 + i) * H2 + tc * 8;
        *(float4*)&g_h2[row] = o0;
        *(float4*)&g_h2[row + 4] = o1;
    }
}

// ---------------- graph segment starts via binary search (batch is sorted) ----------------
__global__ void k_starts(const int* __restrict__ batch) {
    int g = blockIdx.x * blockDim.x + threadIdx.x;
    if (g > N_GRAPHS) return;
    if (g == N_GRAPHS) { g_starts[g] = N_NODES; return; }
    int lo = 0, hi = N_NODES;
    while (lo < hi) {
        int mid = (lo + hi) >> 1;
        if (batch[mid] < g) lo = mid + 1; else hi = mid;
    }
    g_starts[g] = lo;
}

// ---------------- mean-pool + FC fused: out[g] = mean(h2 rows) @ fc_w + fc_b ----------------
__global__ void __launch_bounds__(128) k_pool_fc(const float* __restrict__ fcw,
                                                 const float* __restrict__ fcb,
                                                 float* __restrict__ out) {
    __shared__ float sp[H2];
    int g = blockIdx.x;
    int t = threadIdx.x;
    int s = g_starts[g], e = g_starts[g + 1];
    float acc = 0.0f;
    for (int i = s; i < e; i++) acc += g_h2[(size_t)i * H2 + t];
    float cnt = (float)(e - s);
    sp[t] = acc / fmaxf(cnt, 1.0f);
    __syncthreads();
    float o = fcb[t];
    #pragma unroll 4
    for (int k = 0; k < H2; k++) o += sp[k] * fcw[k * OUT_DIM + t];
    out[(size_t)g * OUT_DIM + t] = o;
}

// ---------------- launch (kernel launches only; graph-capture safe) ----------------
extern "C" void kernel_launch(void* const* d_in, const int* in_sizes, int n_in,
                              void* d_out, int out_size) {
    const float* x     = (const float*)d_in[0];
    const int*   ei    = (const int*)d_in[1];     // JAX default x64-disabled: int32
    const int*   batch = (const int*)d_in[2];     // int32
    const float* W1    = (const float*)d_in[3];
    const float* b1    = (const float*)d_in[4];
    const float* W2    = (const float*)d_in[5];
    const float* b2    = (const float*)d_in[6];
    const float* fcw   = (const float*)d_in[7];
    const float* fcb   = (const float*)d_in[8];
    float*       out   = (float*)d_out;

    // degree + dinv
    k_init_deg<<<(N_NODES + 255) / 256, 256>>>();
    k_count<<<(N_EDGES + 255) / 256, 256>>>(ei);
    k_dinv<<<(N_NODES + 255) / 256, 256>>>();

    // CSR build
    k_scan1<<<SCAN_NBLK, SCAN_B>>>();
    k_scan2<<<1, SCAN_B>>>();
    k_scan3<<<SCAN_NBLK, SCAN_B>>>();
    k_scatter<<<(N_EDGES + 255) / 256, 256>>>(ei);

    // layer 1: transform then aggregate (+b1, relu)
    k_gemm1<<<N_NODES / 64, 256>>>(x, W1);
    k_agg<0><<<(N_NODES * 32 + 255) / 256, 256>>>(b1);

    // layer 2: aggregate in 64-dim, then transform (+b2, relu)
    k_agg<1><<<(N_NODES * 32 + 255) / 256, 256>>>(nullptr);
    k_gemm2<<<N_NODES / 32, 128>>>(W2, b2);

    // pooling + fc
    k_starts<<<(N_GRAPHS + 1 + 255) / 256, 256>>>(batch);
    k_pool_fc<<<N_GRAPHS, 128>>>(fcw, fcb, out);
}

// round 5
// speedup vs baseline: 1.3102x; 1.3102x over previous
#include <cuda_runtime.h>
#include <cuda_fp16.h>
#include <cstdint>

#define N_NODES 200000
#define N_EDGES 3200000
#define N_GRAPHS 4096
#define IN_CH 78
#define H1 64
#define H2 128
#define OUT_DIM 128

#define SCAN_B 512
#define SCAN_NBLK ((N_NODES + SCAN_B - 1) / SCAN_B)   // 391

// ---------------- device scratch (static globals; no allocation) ----------------
__device__ int    g_deg[N_NODES];            // in-degree incl self loop
__device__ float  g_dinv[N_NODES];
__device__ int    g_ptr[N_NODES];            // CSR offsets (exclusive scan of deg-1)
__device__ int    g_cursor[N_NODES];
__device__ int    g_bsum[SCAN_B];
__device__ int2   g_csr[N_EDGES];            // {src, float_bits(norm)} grouped by dst
__device__ __half g_bufA[N_NODES * H1];      // hw1 = x@W1 ; reused for agg2 output
__device__ __half g_h1[N_NODES * H1];        // relu(agg1 + b1)
__device__ __half g_h2[N_NODES * H2];        // relu(agg2@W2 + b2)

// ---------------- degree ----------------
__global__ void k_init_deg() {
    int i = blockIdx.x * blockDim.x + threadIdx.x;
    if (i < N_NODES) g_deg[i] = 1;   // self loop
}

__global__ void k_count(const int* __restrict__ ei) {
    int e4 = blockIdx.x * blockDim.x + threadIdx.x;
    if (e4 < N_EDGES / 4) {
        int4 d = ((const int4*)(ei + N_EDGES))[e4];
        atomicAdd(&g_deg[d.x], 1);
        atomicAdd(&g_deg[d.y], 1);
        atomicAdd(&g_deg[d.z], 1);
        atomicAdd(&g_deg[d.w], 1);
    }
}

// ---------------- scan pass 1 (also computes dinv) ----------------
__global__ void k_scan1() {
    __shared__ int s[SCAN_B];
    int i = blockIdx.x * SCAN_B + threadIdx.x;
    int deg = (i < N_NODES) ? g_deg[i] : 1;
    if (i < N_NODES) g_dinv[i] = rsqrtf((float)deg);
    int v = deg - 1;
    s[threadIdx.x] = v;
    __syncthreads();
    #pragma unroll
    for (int d = 1; d < SCAN_B; d <<= 1) {
        int t = (threadIdx.x >= d) ? s[threadIdx.x - d] : 0;
        __syncthreads();
        s[threadIdx.x] += t;
        __syncthreads();
    }
    if (i < N_NODES) g_ptr[i] = s[threadIdx.x] - v;
    if (threadIdx.x == SCAN_B - 1) g_bsum[blockIdx.x] = s[SCAN_B - 1];
}

__global__ void k_scan2() {
    __shared__ int s[SCAN_B];
    int v = (threadIdx.x < SCAN_NBLK) ? g_bsum[threadIdx.x] : 0;
    s[threadIdx.x] = v;
    __syncthreads();
    #pragma unroll
    for (int d = 1; d < SCAN_B; d <<= 1) {
        int t = (threadIdx.x >= d) ? s[threadIdx.x - d] : 0;
        __syncthreads();
        s[threadIdx.x] += t;
        __syncthreads();
    }
    if (threadIdx.x < SCAN_NBLK) g_bsum[threadIdx.x] = s[threadIdx.x] - v;
}

__global__ void k_scan3() {
    int i = blockIdx.x * SCAN_B + threadIdx.x;
    if (i < N_NODES) {
        int p = g_ptr[i] + g_bsum[blockIdx.x];
        g_ptr[i] = p;
        g_cursor[i] = p;
    }
}

// ---------------- CSR scatter ----------------
__global__ void k_scatter(const int* __restrict__ ei) {
    int e4 = blockIdx.x * blockDim.x + threadIdx.x;
    if (e4 < N_EDGES / 4) {
        int4 s = ((const int4*)ei)[e4];
        int4 d = ((const int4*)(ei + N_EDGES))[e4];
        int p0 = atomicAdd(&g_cursor[d.x], 1);
        g_csr[p0] = make_int2(s.x, __float_as_int(g_dinv[s.x] * g_dinv[d.x]));
        int p1 = atomicAdd(&g_cursor[d.y], 1);
        g_csr[p1] = make_int2(s.y, __float_as_int(g_dinv[s.y] * g_dinv[d.y]));
        int p2 = atomicAdd(&g_cursor[d.z], 1);
        g_csr[p2] = make_int2(s.z, __float_as_int(g_dinv[s.z] * g_dinv[d.z]));
        int p3 = atomicAdd(&g_cursor[d.w], 1);
        g_csr[p3] = make_int2(s.w, __float_as_int(g_dinv[s.w] * g_dinv[d.w]));
    }
}

// ---------------- GEMM1: bufA[N,64] = fp16( x[N,78] @ W1[78,64] ) ----------------
__global__ void __launch_bounds__(256) k_gemm1(const float* __restrict__ X,
                                               const float* __restrict__ W) {
    __shared__ __align__(16) float xs[64 * 79];
    __shared__ __align__(16) float ws[IN_CH * H1];
    int n0 = blockIdx.x * 64;
    const float* xg = X + (size_t)n0 * IN_CH;
    for (int idx = threadIdx.x; idx < 64 * IN_CH; idx += 256) {
        int r = idx / IN_CH, c = idx - r * IN_CH;
        xs[r * 79 + c] = xg[idx];
    }
    for (int idx = threadIdx.x; idx < IN_CH * H1; idx += 256) ws[idx] = W[idx];
    __syncthreads();

    int tn = threadIdx.x >> 4;   // 0..15 -> 4 nodes each
    int tc = threadIdx.x & 15;   // 0..15 -> 4 cols each
    float acc[4][4] = {};
    #pragma unroll 2
    for (int k = 0; k < IN_CH; k++) {
        float4 wq = *(const float4*)&ws[k * H1 + tc * 4];
        #pragma unroll
        for (int i = 0; i < 4; i++) {
            float xv = xs[(tn * 4 + i) * 79 + k];
            acc[i][0] += xv * wq.x;
            acc[i][1] += xv * wq.y;
            acc[i][2] += xv * wq.z;
            acc[i][3] += xv * wq.w;
        }
    }
    #pragma unroll
    for (int i = 0; i < 4; i++) {
        __half2 p0 = __floats2half2_rn(acc[i][0], acc[i][1]);
        __half2 p1 = __floats2half2_rn(acc[i][2], acc[i][3]);
        size_t base = (size_t)(n0 + tn * 4 + i) * H1 + tc * 4;
        *(__half2*)&g_bufA[base]     = p0;
        *(__half2*)&g_bufA[base + 2] = p1;
    }
}

// ---------------- aggregation: one warp per node, fp16 rows, fp32 accum ----------------
// DIR 0: bufA -> h1 (+bias, relu) ; DIR 1: h1 -> bufA
template <int DIR>
__global__ void __launch_bounds__(256) k_agg(const float* __restrict__ bias) {
    const __half2* hp = (const __half2*)((DIR == 0) ? g_bufA : g_h1);
    __half2*       ho = (__half2*)((DIR == 0) ? g_h1 : g_bufA);

    int w = (blockIdx.x * blockDim.x + threadIdx.x) >> 5;
    if (w >= N_NODES) return;
    int lane = threadIdx.x & 31;
    int start = g_ptr[w];
    int cnt = g_deg[w] - 1;
    float di = g_dinv[w];

    float2 sv = __half22float2(hp[(size_t)w * 32 + lane]);
    float w0 = di * di;
    float ax = sv.x * w0, ay = sv.y * w0;

    int e = 0;
    for (; e + 4 <= cnt; e += 4) {
        int2 m0 = g_csr[start + e + 0];
        int2 m1 = g_csr[start + e + 1];
        int2 m2 = g_csr[start + e + 2];
        int2 m3 = g_csr[start + e + 3];
        float2 v0 = __half22float2(hp[(size_t)m0.x * 32 + lane]);
        float2 v1 = __half22float2(hp[(size_t)m1.x * 32 + lane]);
        float2 v2 = __half22float2(hp[(size_t)m2.x * 32 + lane]);
        float2 v3 = __half22float2(hp[(size_t)m3.x * 32 + lane]);
        float w0f = __int_as_float(m0.y), w1f = __int_as_float(m1.y);
        float w2f = __int_as_float(m2.y), w3f = __int_as_float(m3.y);
        ax += w0f * v0.x; ay += w0f * v0.y;
        ax += w1f * v1.x; ay += w1f * v1.y;
        ax += w2f * v2.x; ay += w2f * v2.y;
        ax += w3f * v3.x; ay += w3f * v3.y;
    }
    for (; e < cnt; e++) {
        int2 m = g_csr[start + e];
        float2 v = __half22float2(hp[(size_t)m.x * 32 + lane]);
        float wf = __int_as_float(m.y);
        ax += wf * v.x; ay += wf * v.y;
    }
    if (DIR == 0) {
        ax = fmaxf(ax + bias[2 * lane], 0.0f);
        ay = fmaxf(ay + bias[2 * lane + 1], 0.0f);
    }
    ho[(size_t)w * 32 + lane] = __floats2half2_rn(ax, ay);
}

// ---------------- GEMM2: h2[N,128] = fp16(relu(agg2[N,64] @ W2[64,128] + b2)) ----------------
// 64-node tile, 256 threads. A tile kept in smem as half2 (8.4KB) + W2 float (32KB) = 41.2KB.
__global__ void __launch_bounds__(256) k_gemm2(const float* __restrict__ W2,
                                               const float* __restrict__ b2) {
    __shared__ __align__(16) __half2 as2[64 * 33];   // 64 rows x 32 half2, stride 33 (pad)
    __shared__ __align__(16) float   ws[H1 * H2];
    int n0 = blockIdx.x * 64;

    const __half2* ag = (const __half2*)g_bufA + (size_t)n0 * 32;
    for (int idx = threadIdx.x; idx < 64 * 32; idx += 256) {
        int r = idx >> 5, c = idx & 31;
        as2[r * 33 + c] = ag[idx];
    }
    for (int idx = threadIdx.x; idx < (H1 * H2) / 4; idx += 256)
        ((float4*)ws)[idx] = ((const float4*)W2)[idx];
    __syncthreads();

    int tn = threadIdx.x >> 4;   // 0..15 -> 4 rows each
    int tc = threadIdx.x & 15;   // 0..15 -> 8 cols each
    float acc[4][8] = {};
    #pragma unroll 4
    for (int k2 = 0; k2 < 32; k2++) {            // k = 2*k2, 2*k2+1
        int k0 = 2 * k2;
        float4 wa0 = *(const float4*)&ws[k0 * H2 + tc * 8];
        float4 wa1 = *(const float4*)&ws[k0 * H2 + tc * 8 + 4];
        float4 wb0 = *(const float4*)&ws[(k0 + 1) * H2 + tc * 8];
        float4 wb1 = *(const float4*)&ws[(k0 + 1) * H2 + tc * 8 + 4];
        #pragma unroll
        for (int i = 0; i < 4; i++) {
            float2 av = __half22float2(as2[(tn * 4 + i) * 33 + k2]);
            acc[i][0] += av.x * wa0.x; acc[i][1] += av.x * wa0.y;
            acc[i][2] += av.x * wa0.z; acc[i][3] += av.x * wa0.w;
            acc[i][4] += av.x * wa1.x; acc[i][5] += av.x * wa1.y;
            acc[i][6] += av.x * wa1.z; acc[i][7] += av.x * wa1.w;
            acc[i][0] += av.y * wb0.x; acc[i][1] += av.y * wb0.y;
            acc[i][2] += av.y * wb0.z; acc[i][3] += av.y * wb0.w;
            acc[i][4] += av.y * wb1.x; acc[i][5] += av.y * wb1.y;
            acc[i][6] += av.y * wb1.z; acc[i][7] += av.y * wb1.w;
        }
    }
    float4 bq0 = *(const float4*)&b2[tc * 8];
    float4 bq1 = *(const float4*)&b2[tc * 8 + 4];
    #pragma unroll
    for (int i = 0; i < 4; i++) {
        __half2 h0 = __floats2half2_rn(fmaxf(acc[i][0] + bq0.x, 0.f), fmaxf(acc[i][1] + bq0.y, 0.f));
        __half2 h1v = __floats2half2_rn(fmaxf(acc[i][2] + bq0.z, 0.f), fmaxf(acc[i][3] + bq0.w, 0.f));
        __half2 h2v = __floats2half2_rn(fmaxf(acc[i][4] + bq1.x, 0.f), fmaxf(acc[i][5] + bq1.y, 0.f));
        __half2 h3 = __floats2half2_rn(fmaxf(acc[i][6] + bq1.z, 0.f), fmaxf(acc[i][7] + bq1.w, 0.f));
        uint4 o;
        o.x = *(unsigned*)&h0; o.y = *(unsigned*)&h1v;
        o.z = *(unsigned*)&h2v; o.w = *(unsigned*)&h3;
        *(uint4*)&g_h2[(size_t)(n0 + tn * 4 + i) * H2 + tc * 8] = o;
    }
}

// ---------------- mean-pool + FC fused (binary search for segment bounds inline) ----------------
__global__ void __launch_bounds__(128) k_pool_fc(const int* __restrict__ batch,
                                                 const float* __restrict__ fcw,
                                                 const float* __restrict__ fcb,
                                                 float* __restrict__ out) {
    __shared__ float sp[H2];
    __shared__ int ss[2];
    int g = blockIdx.x;
    int t = threadIdx.x;
    if (t < 2) {
        int target = g + t;           // lower_bound(batch, target)
        int lo = 0, hi = N_NODES;
        while (lo < hi) {
            int mid = (lo + hi) >> 1;
            if (batch[mid] < target) lo = mid + 1; else hi = mid;
        }
        ss[t] = lo;
    }
    __syncthreads();
    int s = ss[0], e = ss[1];
    if (t < 64) {
        const __half2* hp = (const __half2*)g_h2;
        float ax = 0.f, ay = 0.f;
        for (int i = s; i < e; i++) {
            float2 v = __half22float2(hp[(size_t)i * 64 + t]);
            ax += v.x; ay += v.y;
        }
        float inv = 1.0f / fmaxf((float)(e - s), 1.0f);
        sp[2 * t]     = ax * inv;
        sp[2 * t + 1] = ay * inv;
    }
    __syncthreads();
    float o = fcb[t];
    #pragma unroll 4
    for (int k = 0; k < H2; k++) o += sp[k] * fcw[k * OUT_DIM + t];
    out[(size_t)g * OUT_DIM + t] = o;
}

// ---------------- launch (kernel launches only; graph-capture safe) ----------------
extern "C" void kernel_launch(void* const* d_in, const int* in_sizes, int n_in,
                              void* d_out, int out_size) {
    const float* x     = (const float*)d_in[0];
    const int*   ei    = (const int*)d_in[1];     // int32 (JAX x64 disabled)
    const int*   batch = (const int*)d_in[2];
    const float* W1    = (const float*)d_in[3];
    const float* b1    = (const float*)d_in[4];
    const float* W2    = (const float*)d_in[5];
    const float* b2    = (const float*)d_in[6];
    const float* fcw   = (const float*)d_in[7];
    const float* fcb   = (const float*)d_in[8];
    float*       out   = (float*)d_out;

    k_init_deg<<<(N_NODES + 255) / 256, 256>>>();
    k_count<<<(N_EDGES / 4 + 255) / 256, 256>>>(ei);

    k_scan1<<<SCAN_NBLK, SCAN_B>>>();
    k_scan2<<<1, SCAN_B>>>();
    k_scan3<<<SCAN_NBLK, SCAN_B>>>();
    k_scatter<<<(N_EDGES / 4 + 255) / 256, 256>>>(ei);

    k_gemm1<<<N_NODES / 64, 256>>>(x, W1);
    k_agg<0><<<(N_NODES * 32 + 255) / 256, 256>>>(b1);

    k_agg<1><<<(N_NODES * 32 + 255) / 256, 256>>>(nullptr);
    k_gemm2<<<N_NODES / 64, 256>>>(W2, b2);

    k_pool_fc<<<N_GRAPHS, 128>>>(batch, fcw, fcb, out);
}

// round 6
// speedup vs baseline: 1.7802x; 1.3588x over previous
#include <cuda_runtime.h>
#include <cuda_fp16.h>
#include <cstdint>

#define N_NODES 200000
#define N_EDGES 3200000
#define N_GRAPHS 4096
#define IN_CH 78
#define K1P 80            // IN_CH padded to 5 k-tiles of 16
#define H1 64
#define H2 128
#define OUT_DIM 128

#define SCAN_B 512
#define SCAN_NBLK ((N_NODES + SCAN_B - 1) / SCAN_B)   // 391

// ---------------- device scratch (static globals; no allocation) ----------------
__device__ int    g_deg[N_NODES];
__device__ float  g_dinv[N_NODES];
__device__ int    g_ptr[N_NODES];
__device__ int    g_cursor[N_NODES];
__device__ int    g_bsum[SCAN_B];
__device__ int    g_csr[N_EDGES];            // src indices grouped by dst
__device__ __half g_xh[(size_t)N_NODES * K1P];   // x in fp16, K padded to 80
__device__ __half g_W1h[H1 * K1P];           // W1^T fp16 [n=64][k=80]
__device__ __half g_W2h[H2 * H1];            // W2^T fp16 [n=128][k=64]
__device__ __half g_bufA[(size_t)N_NODES * H1]; // p = (x@W1)*dinv ; reused for agg2 out
__device__ __half g_h1[(size_t)N_NODES * H1];   // relu(agg1+b1)*dinv (pre-scaled for layer2)
__device__ __half g_h2[(size_t)N_NODES * H2];   // relu(agg2@W2+b2)

// ---------------- mma.sync wrapper: m16n8k16 row.col f32.f16.f16.f32 ----------------
__device__ __forceinline__ void mma16816(float* c, unsigned a0, unsigned a1,
                                         unsigned a2, unsigned a3,
                                         unsigned b0, unsigned b1) {
    asm volatile(
        "mma.sync.aligned.m16n8k16.row.col.f32.f16.f16.f32 "
        "{%0,%1,%2,%3}, {%4,%5,%6,%7}, {%8,%9}, {%0,%1,%2,%3};"
        : "+f"(c[0]), "+f"(c[1]), "+f"(c[2]), "+f"(c[3])
        : "r"(a0), "r"(a1), "r"(a2), "r"(a3), "r"(b0), "r"(b1));
}

// ---------------- degree ----------------
__global__ void k_init_deg() {
    int i = blockIdx.x * blockDim.x + threadIdx.x;
    if (i < N_NODES) g_deg[i] = 1;   // self loop
}

__global__ void k_count(const int* __restrict__ ei) {
    int e4 = blockIdx.x * blockDim.x + threadIdx.x;
    if (e4 < N_EDGES / 4) {
        int4 d = ((const int4*)(ei + N_EDGES))[e4];
        atomicAdd(&g_deg[d.x], 1);
        atomicAdd(&g_deg[d.y], 1);
        atomicAdd(&g_deg[d.z], 1);
        atomicAdd(&g_deg[d.w], 1);
    }
}

// ---------------- scan pass 1 (also computes dinv) ----------------
__global__ void k_scan1() {
    __shared__ int s[SCAN_B];
    int i = blockIdx.x * SCAN_B + threadIdx.x;
    int deg = (i < N_NODES) ? g_deg[i] : 1;
    if (i < N_NODES) g_dinv[i] = rsqrtf((float)deg);
    int v = deg - 1;
    s[threadIdx.x] = v;
    __syncthreads();
    #pragma unroll
    for (int d = 1; d < SCAN_B; d <<= 1) {
        int t = (threadIdx.x >= d) ? s[threadIdx.x - d] : 0;
        __syncthreads();
        s[threadIdx.x] += t;
        __syncthreads();
    }
    if (i < N_NODES) g_ptr[i] = s[threadIdx.x] - v;
    if (threadIdx.x == SCAN_B - 1) g_bsum[blockIdx.x] = s[SCAN_B - 1];
}

__global__ void k_scan2() {
    __shared__ int s[SCAN_B];
    int v = (threadIdx.x < SCAN_NBLK) ? g_bsum[threadIdx.x] : 0;
    s[threadIdx.x] = v;
    __syncthreads();
    #pragma unroll
    for (int d = 1; d < SCAN_B; d <<= 1) {
        int t = (threadIdx.x >= d) ? s[threadIdx.x - d] : 0;
        __syncthreads();
        s[threadIdx.x] += t;
        __syncthreads();
    }
    if (threadIdx.x < SCAN_NBLK) g_bsum[threadIdx.x] = s[threadIdx.x] - v;
}

__global__ void k_scan3() {
    int i = blockIdx.x * SCAN_B + threadIdx.x;
    if (i < N_NODES) {
        int p = g_ptr[i] + g_bsum[blockIdx.x];
        g_ptr[i] = p;
        g_cursor[i] = p;
    }
}

// ---------------- CSR scatter (src index only) ----------------
__global__ void k_scatter(const int* __restrict__ ei) {
    int e4 = blockIdx.x * blockDim.x + threadIdx.x;
    if (e4 < N_EDGES / 4) {
        int4 s = ((const int4*)ei)[e4];
        int4 d = ((const int4*)(ei + N_EDGES))[e4];
        g_csr[atomicAdd(&g_cursor[d.x], 1)] = s.x;
        g_csr[atomicAdd(&g_cursor[d.y], 1)] = s.y;
        g_csr[atomicAdd(&g_cursor[d.z], 1)] = s.z;
        g_csr[atomicAdd(&g_cursor[d.w], 1)] = s.w;
    }
}

// ---------------- prep: x -> fp16 padded [N,80] ----------------
__global__ void k_xprep(const float* __restrict__ X) {
    size_t idx = (size_t)blockIdx.x * blockDim.x + threadIdx.x;
    if (idx < (size_t)N_NODES * K1P) {
        int row = (int)(idx / K1P), c = (int)(idx % K1P);
        float v = (c < IN_CH) ? X[(size_t)row * IN_CH + c] : 0.0f;
        g_xh[idx] = __float2half(v);
    }
}

// ---------------- prep: W1^T, W2^T -> fp16 ----------------
__global__ void k_wprep(const float* __restrict__ W1, const float* __restrict__ W2) {
    int idx = blockIdx.x * blockDim.x + threadIdx.x;
    if (idx < H1 * K1P) {                     // g_W1h[n][k], k padded
        int n = idx / K1P, k = idx % K1P;
        float v = (k < IN_CH) ? W1[k * H1 + n] : 0.0f;
        g_W1h[idx] = __float2half(v);
    } else if (idx < H1 * K1P + H2 * H1) {    // g_W2h[n][k]
        int j = idx - H1 * K1P;
        int n = j / H1, k = j % H1;
        g_W2h[j] = __float2half(W2[k * H2 + n]);
    }
}

// ---------------- GEMM1 (tensor core): bufA[N,64] = fp16( (xh@W1) * dinv[row] ) ----------------
// tile 128 rows x 64 cols, K=80 (5 ktiles). 8 warps, each 16 rows x 64 cols.
#define ST1 88   // smem stride in halves (44 uints -> conflict-free fragment loads)
__global__ void __launch_bounds__(256) k_gemm1() {
    __shared__ __align__(16) __half xs[128 * ST1];
    __shared__ __align__(16) __half ws[H1 * ST1];
    int n0 = blockIdx.x * 128;

    const unsigned* xg = (const unsigned*)g_xh;
    for (int idx = threadIdx.x; idx < 128 * (K1P / 2); idx += 256) {
        int r = idx / (K1P / 2), c = idx % (K1P / 2);
        unsigned v = (n0 + r < N_NODES) ? xg[(size_t)(n0 + r) * (K1P / 2) + c] : 0u;
        ((unsigned*)xs)[r * (ST1 / 2) + c] = v;
    }
    const unsigned* wg = (const unsigned*)g_W1h;
    for (int idx = threadIdx.x; idx < H1 * (K1P / 2); idx += 256) {
        int r = idx / (K1P / 2), c = idx % (K1P / 2);
        ((unsigned*)ws)[r * (ST1 / 2) + c] = wg[idx];
    }
    __syncthreads();

    int wid = threadIdx.x >> 5, l = threadIdx.x & 31;
    int lr = l >> 2, lc = (l & 3) * 2;
    int arow = wid * 16;
    float acc[8][4] = {};
    #pragma unroll
    for (int kt = 0; kt < 5; kt++) {
        int k0 = kt * 16;
        unsigned a0 = *(unsigned*)&xs[(arow + lr) * ST1 + k0 + lc];
        unsigned a1 = *(unsigned*)&xs[(arow + lr + 8) * ST1 + k0 + lc];
        unsigned a2 = *(unsigned*)&xs[(arow + lr) * ST1 + k0 + lc + 8];
        unsigned a3 = *(unsigned*)&xs[(arow + lr + 8) * ST1 + k0 + lc + 8];
        #pragma unroll
        for (int nt = 0; nt < 8; nt++) {
            unsigned b0 = *(unsigned*)&ws[(nt * 8 + lr) * ST1 + k0 + lc];
            unsigned b1 = *(unsigned*)&ws[(nt * 8 + lr) * ST1 + k0 + lc + 8];
            mma16816(acc[nt], a0, a1, a2, a3, b0, b1);
        }
    }
    int r0 = n0 + arow + lr;
    int r1 = r0 + 8;
    float d0 = (r0 < N_NODES) ? g_dinv[r0] : 0.0f;
    float d1 = (r1 < N_NODES) ? g_dinv[r1] : 0.0f;
    #pragma unroll
    for (int nt = 0; nt < 8; nt++) {
        int col = nt * 8 + lc;
        if (r0 < N_NODES)
            *(__half2*)&g_bufA[(size_t)r0 * H1 + col] =
                __floats2half2_rn(acc[nt][0] * d0, acc[nt][1] * d0);
        if (r1 < N_NODES)
            *(__half2*)&g_bufA[(size_t)r1 * H1 + col] =
                __floats2half2_rn(acc[nt][2] * d1, acc[nt][3] * d1);
    }
}

// ---------------- aggregation: one warp per node, weightless (pre-scaled rows) ----------------
// acc = p[n] + sum_e p[src] ; out = dinv*acc ; DIR0: relu(out+b1)*dinv ; DIR1: out
template <int DIR>
__global__ void __launch_bounds__(256) k_agg(const float* __restrict__ bias) {
    const __half2* hp = (const __half2*)((DIR == 0) ? g_bufA : g_h1);
    __half2*       ho = (__half2*)((DIR == 0) ? g_h1 : g_bufA);

    int w = (blockIdx.x * blockDim.x + threadIdx.x) >> 5;
    if (w >= N_NODES) return;
    int lane = threadIdx.x & 31;
    int start = g_ptr[w];
    int cnt = g_deg[w] - 1;
    float di = g_dinv[w];

    float2 sv = __half22float2(hp[(size_t)w * 32 + lane]);
    float ax = sv.x, ay = sv.y;

    int e = 0;
    for (; e + 8 <= cnt; e += 8) {
        int s0 = g_csr[start + e + 0];
        int s1 = g_csr[start + e + 1];
        int s2 = g_csr[start + e + 2];
        int s3 = g_csr[start + e + 3];
        int s4 = g_csr[start + e + 4];
        int s5 = g_csr[start + e + 5];
        int s6 = g_csr[start + e + 6];
        int s7 = g_csr[start + e + 7];
        float2 v0 = __half22float2(hp[(size_t)s0 * 32 + lane]);
        float2 v1 = __half22float2(hp[(size_t)s1 * 32 + lane]);
        float2 v2 = __half22float2(hp[(size_t)s2 * 32 + lane]);
        float2 v3 = __half22float2(hp[(size_t)s3 * 32 + lane]);
        float2 v4 = __half22float2(hp[(size_t)s4 * 32 + lane]);
        float2 v5 = __half22float2(hp[(size_t)s5 * 32 + lane]);
        float2 v6 = __half22float2(hp[(size_t)s6 * 32 + lane]);
        float2 v7 = __half22float2(hp[(size_t)s7 * 32 + lane]);
        ax += v0.x + v1.x + v2.x + v3.x + v4.x + v5.x + v6.x + v7.x;
        ay += v0.y + v1.y + v2.y + v3.y + v4.y + v5.y + v6.y + v7.y;
    }
    for (; e < cnt; e++) {
        int s = g_csr[start + e];
        float2 v = __half22float2(hp[(size_t)s * 32 + lane]);
        ax += v.x; ay += v.y;
    }
    float ox = di * ax, oy = di * ay;
    if (DIR == 0) {
        ox = fmaxf(ox + bias[2 * lane], 0.0f) * di;
        oy = fmaxf(oy + bias[2 * lane + 1], 0.0f) * di;
    }
    ho[(size_t)w * 32 + lane] = __floats2half2_rn(ox, oy);
}

// ---------------- GEMM2 (tensor core): h2[N,128] = fp16(relu(agg2@W2 + b2)) ----------------
// tile 128 rows x 128 cols, K=64 (4 ktiles). 8 warps (4x2): each 32 rows x 64 cols.
#define ST2 72   // smem stride in halves (36 uints -> conflict-free fragment loads)
__global__ void __launch_bounds__(256) k_gemm2(const float* __restrict__ b2) {
    __shared__ __align__(16) __half as[128 * ST2];
    __shared__ __align__(16) __half ws[H2 * ST2];
    int n0 = blockIdx.x * 128;

    const unsigned* ag = (const unsigned*)g_bufA;
    for (int idx = threadIdx.x; idx < 128 * (H1 / 2); idx += 256) {
        int r = idx / (H1 / 2), c = idx % (H1 / 2);
        unsigned v = (n0 + r < N_NODES) ? ag[(size_t)(n0 + r) * (H1 / 2) + c] : 0u;
        ((unsigned*)as)[r * (ST2 / 2) + c] = v;
    }
    const unsigned* wg = (const unsigned*)g_W2h;
    for (int idx = threadIdx.x; idx < H2 * (H1 / 2); idx += 256) {
        int r = idx / (H1 / 2), c = idx % (H1 / 2);
        ((unsigned*)ws)[r * (ST2 / 2) + c] = wg[idx];
    }
    __syncthreads();

    int wid = threadIdx.x >> 5, l = threadIdx.x & 31;
    int lr = l >> 2, lc = (l & 3) * 2;
    int wm = wid & 3, wn = wid >> 2;
    float acc[2][8][4] = {};
    #pragma unroll
    for (int kt = 0; kt < 4; kt++) {
        int k0 = kt * 16;
        unsigned a[2][4];
        #pragma unroll
        for (int mt = 0; mt < 2; mt++) {
            int arow = wm * 32 + mt * 16;
            a[mt][0] = *(unsigned*)&as[(arow + lr) * ST2 + k0 + lc];
            a[mt][1] = *(unsigned*)&as[(arow + lr + 8) * ST2 + k0 + lc];
            a[mt][2] = *(unsigned*)&as[(arow + lr) * ST2 + k0 + lc + 8];
            a[mt][3] = *(unsigned*)&as[(arow + lr + 8) * ST2 + k0 + lc + 8];
        }
        #pragma unroll
        for (int nt = 0; nt < 8; nt++) {
            int brow = wn * 64 + nt * 8 + lr;
            unsigned b0 = *(unsigned*)&ws[brow * ST2 + k0 + lc];
            unsigned b1 = *(unsigned*)&ws[brow * ST2 + k0 + lc + 8];
            mma16816(acc[0][nt], a[0][0], a[0][1], a[0][2], a[0][3], b0, b1);
            mma16816(acc[1][nt], a[1][0], a[1][1], a[1][2], a[1][3], b0, b1);
        }
    }
    #pragma unroll
    for (int nt = 0; nt < 8; nt++) {
        int col = wn * 64 + nt * 8 + lc;
        float bx = b2[col], by = b2[col + 1];
        #pragma unroll
        for (int mt = 0; mt < 2; mt++) {
            int r0 = n0 + wm * 32 + mt * 16 + lr;
            int r1 = r0 + 8;
            if (r0 < N_NODES)
                *(__half2*)&g_h2[(size_t)r0 * H2 + col] =
                    __floats2half2_rn(fmaxf(acc[mt][nt][0] + bx, 0.f),
                                      fmaxf(acc[mt][nt][1] + by, 0.f));
            if (r1 < N_NODES)
                *(__half2*)&g_h2[(size_t)r1 * H2 + col] =
                    __floats2half2_rn(fmaxf(acc[mt][nt][2] + bx, 0.f),
                                      fmaxf(acc[mt][nt][3] + by, 0.f));
        }
    }
}

// ---------------- mean-pool + FC fused ----------------
__global__ void __launch_bounds__(128) k_pool_fc(const int* __restrict__ batch,
                                                 const float* __restrict__ fcw,
                                                 const float* __restrict__ fcb,
                                                 float* __restrict__ out) {
    __shared__ float sp[H2];
    __shared__ int ss[2];
    int g = blockIdx.x;
    int t = threadIdx.x;
    if (t < 2) {
        int target = g + t;
        int lo = 0, hi = N_NODES;
        while (lo < hi) {
            int mid = (lo + hi) >> 1;
            if (batch[mid] < target) lo = mid + 1; else hi = mid;
        }
        ss[t] = lo;
    }
    __syncthreads();
    int s = ss[0], e = ss[1];
    if (t < 64) {
        const __half2* hp = (const __half2*)g_h2;
        float ax = 0.f, ay = 0.f;
        for (int i = s; i < e; i++) {
            float2 v = __half22float2(hp[(size_t)i * 64 + t]);
            ax += v.x; ay += v.y;
        }
        float inv = 1.0f / fmaxf((float)(e - s), 1.0f);
        sp[2 * t]     = ax * inv;
        sp[2 * t + 1] = ay * inv;
    }
    __syncthreads();
    float o = fcb[t];
    #pragma unroll 4
    for (int k = 0; k < H2; k++) o += sp[k] * fcw[k * OUT_DIM + t];
    out[(size_t)g * OUT_DIM + t] = o;
}

// ---------------- launch ----------------
extern "C" void kernel_launch(void* const* d_in, const int* in_sizes, int n_in,
                              void* d_out, int out_size) {
    const float* x     = (const float*)d_in[0];
    const int*   ei    = (const int*)d_in[1];
    const int*   batch = (const int*)d_in[2];
    const float* W1    = (const float*)d_in[3];
    const float* b1    = (const float*)d_in[4];
    const float* W2    = (const float*)d_in[5];
    const float* b2    = (const float*)d_in[6];
    const float* fcw   = (const float*)d_in[7];
    const float* fcb   = (const float*)d_in[8];
    float*       out   = (float*)d_out;

    k_init_deg<<<(N_NODES + 255) / 256, 256>>>();
    k_count<<<(N_EDGES / 4 + 255) / 256, 256>>>(ei);

    k_scan1<<<SCAN_NBLK, SCAN_B>>>();
    k_scan2<<<1, SCAN_B>>>();
    k_scan3<<<SCAN_NBLK, SCAN_B>>>();
    k_scatter<<<(N_EDGES / 4 + 255) / 256, 256>>>(ei);

    k_xprep<<<(int)(((size_t)N_NODES * K1P + 255) / 256), 256>>>(x);
    k_wprep<<<(H1 * K1P + H2 * H1 + 255) / 256, 256>>>(W1, W2);

    k_gemm1<<<(N_NODES + 127) / 128, 256>>>();
    k_agg<0><<<(N_NODES * 32 + 255) / 256, 256>>>(b1);

    k_agg<1><<<(N_NODES * 32 + 255) / 256, 256>>>(nullptr);
    k_gemm2<<<(N_NODES + 127) / 128, 256>>>(b2);

    k_pool_fc<<<N_GRAPHS, 128>>>(batch, fcw, fcb, out);
}